// round 3
// baseline (speedup 1.0000x reference)
#include <cuda_runtime.h>
#include <cstdint>

#define BN 8
#define CN 16
#define HN 96
#define WN 96
#define HW (HN*WN)
#define CHW (CN*HW)
#define NPIX (BN*HW)          // 73728
#define HID 128
#define YDIM 48

// scratch for pre-masked updated state (allocation-free rule: device global)
__device__ float g_tmp[BN*CHW];

// ---------------- threefry2x32 (JAX-compatible) ----------------
__host__ __device__ __forceinline__ uint32_t rotl32(uint32_t x, int r) {
#ifdef __CUDA_ARCH__
    return __funnelshift_l(x, x, r);
#else
    return (x << r) | (x >> (32 - r));
#endif
}

__host__ __device__ __forceinline__ void tf_round(uint32_t& x0, uint32_t& x1, int r) {
    x0 += x1; x1 = rotl32(x1, r); x1 ^= x0;
}

struct U2 { uint32_t x, y; };

__host__ __device__ __forceinline__ U2 threefry2x32(uint32_t k0, uint32_t k1,
                                                    uint32_t x0, uint32_t x1) {
    uint32_t k2 = k0 ^ k1 ^ 0x1BD11BDAu;
    x0 += k0; x1 += k1;
    tf_round(x0,x1,13); tf_round(x0,x1,15); tf_round(x0,x1,26); tf_round(x0,x1, 6);
    x0 += k1; x1 += k2 + 1u;
    tf_round(x0,x1,17); tf_round(x0,x1,29); tf_round(x0,x1,16); tf_round(x0,x1,24);
    x0 += k2; x1 += k0 + 2u;
    tf_round(x0,x1,13); tf_round(x0,x1,15); tf_round(x0,x1,26); tf_round(x0,x1, 6);
    x0 += k0; x1 += k1 + 3u;
    tf_round(x0,x1,17); tf_round(x0,x1,29); tf_round(x0,x1,16); tf_round(x0,x1,24);
    x0 += k1; x1 += k2 + 4u;
    tf_round(x0,x1,13); tf_round(x0,x1,15); tf_round(x0,x1,26); tf_round(x0,x1, 6);
    x0 += k2; x1 += k0 + 5u;
    U2 r; r.x = x0; r.y = x1; return r;
}

// jax_threefry_partitionable=True: bits(key, i) = o0 ^ o1 of threefry(key, hi=0, lo=i)
// uniform(key,i) > 0.5  <=>  (bits >> 9) > 0x400000
__device__ __forceinline__ float upd_mask_val(uint32_t k0, uint32_t k1, uint32_t idx) {
    U2 r = threefry2x32(k0, k1, 0u, idx);
    uint32_t bits = r.x ^ r.y;
    return ((bits >> 9) > 0x400000u) ? 1.0f : 0.0f;
}

// ---------------- K1: perception + 2 GEMMs + stochastic update ----------------
__global__ __launch_bounds__(256)
void k_update(const float* __restrict__ xin,
              const float* __restrict__ w2,
              const float* __restrict__ w3,
              uint32_t key0, uint32_t key1) {
    __shared__ __align__(16) float s_w2[HID*YDIM];   // 24 KB, row o: 48 floats
    __shared__ __align__(16) float s_w3[CN*HID];     // 8 KB, row c: 128 floats

    int tid = threadIdx.x;
    for (int i = tid; i < HID*YDIM; i += 256) s_w2[i] = w2[i];
    for (int i = tid; i < CN*HID;  i += 256) s_w3[i] = w3[i];
    __syncthreads();

    int p = blockIdx.x * 256 + tid;      // pixel id
    if (p >= NPIX) return;
    int b  = p / HW;
    int hw = p - b * HW;
    int h  = hw / WN, w = hw - h * WN;

    const float* xb = xin + (size_t)b * CHW;

    // perception: y[3c]=x_c, y[3c+1]=sobel_x, y[3c+2]=sobel_y (cross-correlation, zero pad)
    float y[YDIM];
    #pragma unroll
    for (int c = 0; c < CN; c++) {
        const float* xp = xb + c * HW;
        float n[3][3];
        #pragma unroll
        for (int di = 0; di < 3; di++) {
            #pragma unroll
            for (int dj = 0; dj < 3; dj++) {
                int hh = h + di - 1, ww = w + dj - 1;
                n[di][dj] = (hh >= 0 && hh < HN && ww >= 0 && ww < WN)
                            ? __ldg(xp + hh * WN + ww) : 0.0f;
            }
        }
        y[3*c+0] = n[1][1];
        float cs0 = n[0][0] + 2.0f*n[1][0] + n[2][0];
        float cs2 = n[0][2] + 2.0f*n[1][2] + n[2][2];
        y[3*c+1] = (cs2 - cs0) * 0.125f;
        float rs0 = n[0][0] + 2.0f*n[0][1] + n[0][2];
        float rs2 = n[2][0] + 2.0f*n[2][1] + n[2][2];
        y[3*c+2] = (rs2 - rs0) * 0.125f;
    }

    float d[CN];
    #pragma unroll
    for (int c = 0; c < CN; c++) d[c] = 0.0f;

    // h = relu(W2 @ y); d = W3 @ h   (process 4 hidden channels per iter)
    #pragma unroll 1
    for (int o = 0; o < HID; o += 4) {
        float hv[4];
        #pragma unroll
        for (int u = 0; u < 4; u++) {
            const float4* wr = (const float4*)(s_w2 + (o + u) * YDIM);
            float a0 = 0.f, a1 = 0.f, a2 = 0.f, a3 = 0.f;
            #pragma unroll
            for (int k = 0; k < YDIM/4; k++) {
                float4 wv = wr[k];
                a0 = fmaf(wv.x, y[4*k+0], a0);
                a1 = fmaf(wv.y, y[4*k+1], a1);
                a2 = fmaf(wv.z, y[4*k+2], a2);
                a3 = fmaf(wv.w, y[4*k+3], a3);
            }
            hv[u] = fmaxf((a0 + a1) + (a2 + a3), 0.0f);
        }
        #pragma unroll
        for (int c = 0; c < CN; c++) {
            float4 wv = *(const float4*)(s_w3 + c * HID + o);
            d[c] = fmaf(wv.x, hv[0], fmaf(wv.y, hv[1],
                   fmaf(wv.z, hv[2], fmaf(wv.w, hv[3], d[c]))));
        }
    }

    // stochastic update: x_tmp = x + mask * d   (mask per (b,c,h,w) element)
    uint32_t base = (uint32_t)(b * CHW + hw);
    #pragma unroll
    for (int c = 0; c < CN; c++) {
        float m = upd_mask_val(key0, key1, base + (uint32_t)(c * HW));
        g_tmp[b * CHW + c * HW + hw] = y[3*c] + m * d[c];
    }
}

// ---------------- K2: alive gating (pre & post maxpool3) + write frame ----------------
__global__ __launch_bounds__(256)
void k_mask(const float* __restrict__ xold, float* __restrict__ xout) {
    int p = blockIdx.x * 256 + threadIdx.x;
    if (p >= NPIX) return;
    int b  = p / HW;
    int hw = p - b * HW;
    int h  = hw / WN, w = hw - h * WN;

    const float* a_old = xold  + (size_t)b * CHW + 3 * HW;
    const float* a_new = g_tmp + (size_t)b * CHW + 3 * HW;

    float mo = -1e30f, mn = -1e30f;
    #pragma unroll
    for (int di = -1; di <= 1; di++) {
        #pragma unroll
        for (int dj = -1; dj <= 1; dj++) {
            int hh = h + di, ww = w + dj;
            if (hh >= 0 && hh < HN && ww >= 0 && ww < WN) {
                int off = hh * WN + ww;
                mo = fmaxf(mo, __ldg(a_old + off));
                mn = fmaxf(mn, __ldg(a_new + off));
            }
        }
    }
    float m = (mo > 0.1f && mn > 0.1f) ? 1.0f : 0.0f;

    #pragma unroll
    for (int c = 0; c < CN; c++) {
        int idx = b * CHW + c * HW + hw;
        xout[idx] = g_tmp[idx] * m;
    }
}

// ---------------- launch ----------------
extern "C" void kernel_launch(void* const* d_in, const int* in_sizes, int n_in,
                              void* d_out, int out_size) {
    const float* x  = nullptr;
    const float* w2 = nullptr;
    const float* w3 = nullptr;
    for (int i = 0; i < n_in; i++) {
        if      (in_sizes[i] == BN*CHW)   x  = (const float*)d_in[i];
        else if (in_sizes[i] == HID*YDIM) w2 = (const float*)d_in[i];
        else if (in_sizes[i] == CN*HID)   w3 = (const float*)d_in[i];
    }
    float* out = (float*)d_out;
    int T = out_size / (BN * CHW);   // 24

    const int grid = NPIX / 256;     // 288
    const float* prev = x;
    for (int t = 0; t < T; t++) {
        // step key: jax.random.split(key(42), T)[t] under partitionable threefry
        U2 key = threefry2x32(0u, 42u, 0u, (uint32_t)t);
        k_update<<<grid, 256>>>(prev, w2, w3, key.x, key.y);
        float* dst = out + (size_t)t * BN * CHW;
        k_mask<<<grid, 256>>>(prev, dst);
        prev = dst;
    }
}